// round 3
// baseline (speedup 1.0000x reference)
#include <cuda_runtime.h>
#include <cstdint>

#define BS 32
#define NN 1024
#define FO 128
#define NWORDS (NN / 32)
#define ROWS_PER_BLOCK 64
#define ROWS_PER_WARP 4
#define MAIN_THREADS 512

// Scratch (no allocations allowed): 128KB bits + 512KB precompute + means
__device__ uint32_t g_adjw[NN * NWORDS];
__device__ float4   g_pre[BS * NN];     // {s2, exp(s2), exp(s2)*x, s1}
__device__ float    g_meanx[BS];

// ---------------------------------------------------------------------------
// Kernel 1: pack adjacency int32 -> bitmask via ballot (coalesced reads)
// ---------------------------------------------------------------------------
__global__ void k_pack(const int* __restrict__ adj) {
    int idx = blockIdx.x * blockDim.x + threadIdx.x;   // 0 .. NN*NN-1
    int v = adj[idx];
    unsigned m = __ballot_sync(0xffffffffu, v > 0);
    if ((threadIdx.x & 31) == 0) g_adjw[idx >> 5] = m;
}

// ---------------------------------------------------------------------------
// Kernel 2: per-batch precompute of s1, s2, exp(s2), exp(s2)*x, mean(x).
// c1 = W . a[:F], c2 = W . a[F:] reduced per block (one block per batch).
// ---------------------------------------------------------------------------
__global__ void k_pre(const float* __restrict__ x, const float* __restrict__ W,
                      const float* __restrict__ a) {
    int b = blockIdx.x;
    int tid = threadIdx.x;                 // 256 threads
    __shared__ float red[256];
    __shared__ float sc1, sc2, smean;

    float p = (tid < FO) ? W[tid] * a[tid] : 0.f;
    red[tid] = p; __syncthreads();
    for (int s = 128; s > 0; s >>= 1) { if (tid < s) red[tid] += red[tid + s]; __syncthreads(); }
    if (tid == 0) sc1 = red[0];
    __syncthreads();

    p = (tid < FO) ? W[tid] * a[FO + tid] : 0.f;
    red[tid] = p; __syncthreads();
    for (int s = 128; s > 0; s >>= 1) { if (tid < s) red[tid] += red[tid + s]; __syncthreads(); }
    if (tid == 0) sc2 = red[0];
    __syncthreads();

    const float* xb = x + b * NN;
    float sx = 0.f;
    for (int n = tid; n < NN; n += 256) sx += xb[n];
    red[tid] = sx; __syncthreads();
    for (int s = 128; s > 0; s >>= 1) { if (tid < s) red[tid] += red[tid + s]; __syncthreads(); }
    if (tid == 0) { smean = red[0] * (1.0f / NN); g_meanx[b] = smean; }
    __syncthreads();

    float c1 = sc1, c2 = sc2;
    for (int n = tid; n < NN; n += 256) {
        float xv = xb[n];
        float s2 = xv * c2;
        float e2 = __expf(s2);
        g_pre[b * NN + n] = make_float4(s2, e2, e2 * xv, xv * c1);
    }
}

// ---------------------------------------------------------------------------
// Kernel 3: main. One warp handles 4 rows; 64 rows / block; grid (16, 32).
// Inner loop: predicated accumulation of E2 / E2*x over shared tiles,
// adjacency bit from a broadcast shared word. No exp in the loop.
// ---------------------------------------------------------------------------
__device__ __forceinline__ float elu1(float v) {
    return v > 0.f ? v : expm1f(v);
}

__global__ void __launch_bounds__(MAIN_THREADS) k_main(const float* __restrict__ W,
                                                       float* __restrict__ out) {
    __shared__ float4   s_pre[NN];                         // 16 KB
    __shared__ uint32_t s_adjw[ROWS_PER_BLOCK * NWORDS];   // 8 KB
    __shared__ float    s_W[FO];                           // 512 B

    int b    = blockIdx.y;
    int row0 = blockIdx.x * ROWS_PER_BLOCK;
    int tid  = threadIdx.x;
    int lane = tid & 31;
    int wid  = tid >> 5;

    for (int t = tid; t < NN; t += MAIN_THREADS)
        s_pre[t] = g_pre[b * NN + t];
    for (int t = tid; t < ROWS_PER_BLOCK * NWORDS; t += MAIN_THREADS)
        s_adjw[t] = g_adjw[row0 * NWORDS + t];
    if (tid < FO) s_W[tid] = W[tid];
    __syncthreads();

    int ir = wid * ROWS_PER_WARP;   // local row base for this warp

    float thr[ROWS_PER_WARP];
    float den[ROWS_PER_WARP];
    float num[ROWS_PER_WARP];
#pragma unroll
    for (int r = 0; r < ROWS_PER_WARP; r++) {
        thr[r] = -s_pre[row0 + ir + r].w;   // kept iff s2_j > -s1_i
        den[r] = 0.f;
        num[r] = 0.f;
    }

#pragma unroll 4
    for (int k = 0; k < NWORDS; k++) {
        float4 q = s_pre[k * 32 + lane];    // {s2, E2, E2*x, s1}
#pragma unroll
        for (int r = 0; r < ROWS_PER_WARP; r++) {
            uint32_t w = s_adjw[(ir + r) * NWORDS + k];   // broadcast
            bool keep = ((w >> lane) & 1u) && (q.x > thr[r]);
            if (keep) { den[r] += q.y; num[r] += q.z; }
        }
    }

    float meanx = g_meanx[b];
    const float4* W4 = reinterpret_cast<const float4*>(s_W);
    float4 wv = W4[lane];

#pragma unroll
    for (int r = 0; r < ROWS_PER_WARP; r++) {
        float d = den[r], nm = num[r];
#pragma unroll
        for (int o = 16; o > 0; o >>= 1) {
            d  += __shfl_xor_sync(0xffffffffu, d,  o);
            nm += __shfl_xor_sync(0xffffffffu, nm, o);
        }
        float y = (d > 0.f) ? (nm / d) : meanx;

        int i = row0 + ir + r;
        float4 z;
        z.x = elu1(y * wv.x);
        z.y = elu1(y * wv.y);
        z.z = elu1(y * wv.z);
        z.w = elu1(y * wv.w);
        reinterpret_cast<float4*>(out)[(size_t)(b * NN + i) * (FO / 4) + lane] = z;
    }
}

// ---------------------------------------------------------------------------
// Launch: inputs per metadata order: input, adj, ext_input, side_input, W, a
// ---------------------------------------------------------------------------
extern "C" void kernel_launch(void* const* d_in, const int* in_sizes, int n_in,
                              void* d_out, int out_size) {
    const float* input = (const float*)d_in[0];
    const int*   adj   = (const int*)  d_in[1];
    const float* W     = (const float*)d_in[4];
    const float* a     = (const float*)d_in[5];
    float* out = (float*)d_out;

    k_pack<<<(NN * NN) / 256, 256>>>(adj);
    k_pre<<<BS, 256>>>(input, W, a);
    k_main<<<dim3(NN / ROWS_PER_BLOCK, BS), MAIN_THREADS>>>(W, out);
}

// round 4
// speedup vs baseline: 1.0932x; 1.0932x over previous
#include <cuda_runtime.h>
#include <cstdint>

#define BS 32
#define NN 1024
#define FO 128
#define NWORDS 32
#define PACK_BLOCKS 512

#define RW 4                      // rows per warp
#define BW 4                      // batches per block (and per warp)
#define WARPS 8
#define ROWS_PER_BLOCK (RW * WARPS)   // 32

// Scratch (__device__ globals; no allocations allowed)
__device__ uint32_t g_adjw[NN * NWORDS];   // 128 KB packed adjacency
__device__ float    g_c1, g_c2;
__device__ float    g_meanx[BS];

// ---------------------------------------------------------------------------
// Setup kernel (fused): adjacency bit-pack (MLP=8 per warp) + scalars c1,c2 +
// per-batch mean(x).
// ---------------------------------------------------------------------------
__global__ void __launch_bounds__(256) k_setup(const int* __restrict__ adj,
                                               const float* __restrict__ x,
                                               const float* __restrict__ W,
                                               const float* __restrict__ a) {
    int bid = blockIdx.x;
    int tid = threadIdx.x;

    if (bid < PACK_BLOCKS) {
        // 8 warps/block, each warp packs 8 consecutive words (256 ints).
        int warp = tid >> 5, lane = tid & 31;
        int wbase = (bid * WARPS + warp) * 8;       // first word index
        int ebase = wbase * 32;                     // first element index
        int v[8];
#pragma unroll
        for (int r = 0; r < 8; r++)
            v[r] = adj[ebase + r * 32 + lane];      // 8 independent coalesced LDG
        uint32_t myw = 0;
#pragma unroll
        for (int r = 0; r < 8; r++) {
            unsigned m = __ballot_sync(0xffffffffu, v[r] > 0);
            if (lane == r) myw = m;
        }
        if (lane < 8) g_adjw[wbase + lane] = myw;
        return;
    }

    __shared__ float red[256];

    if (bid < PACK_BLOCKS + BS) {
        // per-batch mean of x
        int b = bid - PACK_BLOCKS;
        float s = 0.f;
        for (int n = tid; n < NN; n += 256) s += x[b * NN + n];
        red[tid] = s; __syncthreads();
        for (int st = 128; st > 0; st >>= 1) {
            if (tid < st) red[tid] += red[tid + st];
            __syncthreads();
        }
        if (tid == 0) g_meanx[b] = red[0] * (1.0f / NN);
        return;
    }

    // last block: c1 = W.a[:F], c2 = W.a[F:]
    float p = (tid < FO) ? W[tid] * a[tid] : 0.f;
    red[tid] = p; __syncthreads();
    for (int st = 128; st > 0; st >>= 1) {
        if (tid < st) red[tid] += red[tid + st];
        __syncthreads();
    }
    if (tid == 0) g_c1 = red[0];
    __syncthreads();

    p = (tid < FO) ? W[tid] * a[FO + tid] : 0.f;
    red[tid] = p; __syncthreads();
    for (int st = 128; st > 0; st >>= 1) {
        if (tid < st) red[tid] += red[tid + st];
        __syncthreads();
    }
    if (tid == 0) g_c2 = red[0];
}

// ---------------------------------------------------------------------------
// Main kernel: warp = 4 rows x 4 batches. Bit-test amortized over batches,
// s2/E2 recomputed in-loop (2 instrs) from shared x. Exact same keep-predicate
// (s2_j > -c1*x_i) as the passing kernel.
// ---------------------------------------------------------------------------
__device__ __forceinline__ float elu1(float v) {
    return v > 0.f ? v : expm1f(v);
}

__global__ void __launch_bounds__(256) k_main(const float* __restrict__ x,
                                              const float* __restrict__ W,
                                              float* __restrict__ out) {
    __shared__ float    s_x[BW][NN];                        // 16 KB
    __shared__ uint32_t s_adjw[ROWS_PER_BLOCK * NWORDS];    // 4 KB
    __shared__ float    s_W[FO];                            // 512 B

    int tid  = threadIdx.x;
    int lane = tid & 31;
    int warp = tid >> 5;
    int row0 = blockIdx.x * ROWS_PER_BLOCK;
    int b0   = blockIdx.y * BW;

    // cooperative loads
    {
        const float4* src = reinterpret_cast<const float4*>(x + (size_t)b0 * NN);
        float4* dst = reinterpret_cast<float4*>(&s_x[0][0]);
        for (int t = tid; t < BW * NN / 4; t += 256) dst[t] = src[t];
    }
    for (int t = tid; t < ROWS_PER_BLOCK * NWORDS; t += 256)
        s_adjw[t] = g_adjw[row0 * NWORDS + t];
    if (tid < FO) s_W[tid] = W[tid];
    __syncthreads();

    const float c1 = g_c1, c2 = g_c2;
    const int ir = warp * RW;

    float thr[RW][BW], den[RW][BW], num[RW][BW];
#pragma unroll
    for (int r = 0; r < RW; r++)
#pragma unroll
        for (int b = 0; b < BW; b++) {
            thr[r][b] = -c1 * s_x[b][row0 + ir + r];
            den[r][b] = 0.f;
            num[r][b] = 0.f;
        }

#pragma unroll 2
    for (int k = 0; k < NWORDS; k++) {
        bool bp[RW];
#pragma unroll
        for (int r = 0; r < RW; r++) {
            uint32_t w = s_adjw[(ir + r) * NWORDS + k];     // broadcast LDS
            bp[r] = ((int)(w << (31 - lane))) < 0;          // SHF + ISETP
        }
#pragma unroll
        for (int b = 0; b < BW; b++) {
            float xv = s_x[b][k * 32 + lane];
            float s2 = c2 * xv;
            float e2 = __expf(s2);
#pragma unroll
            for (int r = 0; r < RW; r++) {
                if (bp[r] && (s2 > thr[r][b])) {            // FSETP.AND
                    den[r][b] += e2;                        // @p FADD
                    num[r][b] = fmaf(e2, xv, num[r][b]);    // @p FFMA
                }
            }
        }
    }

    float meanx[BW];
#pragma unroll
    for (int b = 0; b < BW; b++) meanx[b] = g_meanx[b0 + b];

    const float4 wv = reinterpret_cast<const float4*>(s_W)[lane];

#pragma unroll
    for (int r = 0; r < RW; r++) {
        int i = row0 + ir + r;
#pragma unroll
        for (int b = 0; b < BW; b++) {
            float d = den[r][b], nm = num[r][b];
#pragma unroll
            for (int o = 16; o > 0; o >>= 1) {
                d  += __shfl_xor_sync(0xffffffffu, d,  o);
                nm += __shfl_xor_sync(0xffffffffu, nm, o);
            }
            float y = (d > 0.f) ? (nm / d) : meanx[b];
            float4 z;
            z.x = elu1(y * wv.x);
            z.y = elu1(y * wv.y);
            z.z = elu1(y * wv.z);
            z.w = elu1(y * wv.w);
            reinterpret_cast<float4*>(out)[((size_t)(b0 + b) * NN + i) * (FO / 4) + lane] = z;
        }
    }
}

// ---------------------------------------------------------------------------
// Inputs per metadata order: input, adj, ext_input, side_input, W, a
// ---------------------------------------------------------------------------
extern "C" void kernel_launch(void* const* d_in, const int* in_sizes, int n_in,
                              void* d_out, int out_size) {
    const float* input = (const float*)d_in[0];
    const int*   adj   = (const int*)  d_in[1];
    const float* W     = (const float*)d_in[4];
    const float* a     = (const float*)d_in[5];
    float* out = (float*)d_out;

    k_setup<<<PACK_BLOCKS + BS + 1, 256>>>(adj, input, W, a);
    k_main<<<dim3(NN / ROWS_PER_BLOCK, BS / BW), 256>>>(input, W, out);
}